// round 1
// baseline (speedup 1.0000x reference)
#include <cuda_runtime.h>
#include <math.h>
#include <stdint.h>

#define NN 50000
#define NE 800000
#define DH 128
#define DO 47
#define OPB (NN*(DH+DO+DO))        /* 11,100,000 floats per branch in d_out */
#define NB_SCAN ((NN + 1023)/1024) /* 49 */

// ---------------- scratch (device globals: allocation-free) ----------------
__device__ float g_x2[2*NN*DH];   // layer0 input [x | x_noisy]; reused as h2
__device__ float g_t [2*NN*DH];   // x @ W_l^T   (to be aggregated)
__device__ float g_r [2*NN*DH];   // x @ W_r^T   (self term)
__device__ float g_h [2*NN*DH];   // h1
__device__ float g_t2[2*NN*DO];
__device__ float g_r2[2*NN*DO];
__device__ int   g_deg[NN];
__device__ int   g_off[NN+1];
__device__ int   g_pos[NN];
__device__ int   g_csr[NE];
__device__ int   g_bsum[64];

// ---------------- noise branch input ----------------
// xn = x + sign(x) * (noise/max(||noise||,1e-12)) * 0.1 ; also copies x.
__global__ void k_noise(const float* __restrict__ x, const float* __restrict__ noise) {
    int w = (blockIdx.x*blockDim.x + threadIdx.x) >> 5;
    int lane = threadIdx.x & 31;
    if (w >= NN) return;
    const float4 nv = *(const float4*)(noise + (size_t)w*DH + lane*4);
    float ss = nv.x*nv.x + nv.y*nv.y + nv.z*nv.z + nv.w*nv.w;
    #pragma unroll
    for (int o = 16; o; o >>= 1) ss += __shfl_xor_sync(0xffffffffu, ss, o);
    float sc = 0.1f / fmaxf(sqrtf(ss), 1e-12f);
    float4 xv = *(const float4*)(x + (size_t)w*DH + lane*4);
    float4 xn;
    xn.x = xv.x + ((xv.x>0.f)?1.f:((xv.x<0.f)?-1.f:0.f)) * nv.x * sc;
    xn.y = xv.y + ((xv.y>0.f)?1.f:((xv.y<0.f)?-1.f:0.f)) * nv.y * sc;
    xn.z = xv.z + ((xv.z>0.f)?1.f:((xv.z<0.f)?-1.f:0.f)) * nv.z * sc;
    xn.w = xv.w + ((xv.w>0.f)?1.f:((xv.w<0.f)?-1.f:0.f)) * nv.w * sc;
    *(float4*)(g_x2 + (size_t)w*DH        + lane*4) = xv;
    *(float4*)(g_x2 + (size_t)(NN+w)*DH   + lane*4) = xn;
}

// ---------------- CSR build ----------------
__global__ void k_zero() {
    int i = blockIdx.x*blockDim.x + threadIdx.x;
    if (i < NN) g_deg[i] = 0;
    if (i < 64) g_bsum[i] = 0;
}
__global__ void k_hist(const int* __restrict__ ei) {
    int e = blockIdx.x*blockDim.x + threadIdx.x;
    if (e < NE) atomicAdd(&g_deg[ei[NE + e]], 1);
}
__global__ void k_scan1() {
    __shared__ int s[1024];
    int tid = threadIdx.x;
    int gid = blockIdx.x*1024 + tid;
    int v = (gid < NN) ? g_deg[gid] : 0;
    s[tid] = v; __syncthreads();
    for (int o = 1; o < 1024; o <<= 1) {
        int t = (tid >= o) ? s[tid-o] : 0;
        __syncthreads();
        s[tid] += t;
        __syncthreads();
    }
    if (gid < NN) g_off[gid+1] = s[tid];
    if (tid == 1023) g_bsum[blockIdx.x] = s[1023];
}
__global__ void k_scan2() {   // one block of 64 threads: exclusive scan of block sums
    __shared__ int s[64];
    int tid = threadIdx.x;
    int v = g_bsum[tid];
    s[tid] = v; __syncthreads();
    for (int o = 1; o < 64; o <<= 1) {
        int t = (tid >= o) ? s[tid-o] : 0;
        __syncthreads();
        s[tid] += t;
        __syncthreads();
    }
    g_bsum[tid] = s[tid] - v;
}
__global__ void k_scan3() {
    int gid = blockIdx.x*1024 + threadIdx.x;
    if (gid >= NN) return;
    int incl = g_off[gid+1] + g_bsum[blockIdx.x];
    g_off[gid+1] = incl;
    g_pos[gid]   = incl - g_deg[gid];
    if (gid == 0) g_off[0] = 0;
}
__global__ void k_fill(const int* __restrict__ ei) {
    int e = blockIdx.x*blockDim.x + threadIdx.x;
    if (e < NE) {
        int dst = ei[NE + e];
        int p = atomicAdd(&g_pos[dst], 1);
        g_csr[p] = ei[e];
    }
}

// ---------------- fp32 sgemm: C[M,NO] = X[M,128] @ W[NO,128]^T ----------------
#define BM 128
#define BN 128
#define BK 16
__global__ void __launch_bounds__(256) k_gemm(
    const float* __restrict__ X, const float* __restrict__ W,
    float* __restrict__ C, int M, int NO)
{
    __shared__ float As[BK][BM+4];
    __shared__ float Bs[BK][BN+4];
    int tid = threadIdx.x;
    int bm = blockIdx.x * BM;
    int bn = blockIdx.y * BN;
    int ty = tid >> 4, tx = tid & 15;
    int rm0 = ty*4, rm1 = 64 + ty*4;
    int cn0 = tx*4, cn1 = 64 + tx*4;

    float acc[8][8];
    #pragma unroll
    for (int i = 0; i < 8; i++)
        #pragma unroll
        for (int j = 0; j < 8; j++) acc[i][j] = 0.f;

    for (int k0 = 0; k0 < 128; k0 += BK) {
        #pragma unroll
        for (int r = 0; r < 2; r++) {
            int v = tid + r*256;
            int row = v >> 2;
            int kq  = (v & 3) * 4;
            int gm = bm + row;
            float4 f = (gm < M) ? *(const float4*)(X + (size_t)gm*128 + k0 + kq)
                                : make_float4(0.f,0.f,0.f,0.f);
            As[kq+0][row] = f.x; As[kq+1][row] = f.y;
            As[kq+2][row] = f.z; As[kq+3][row] = f.w;
        }
        #pragma unroll
        for (int r = 0; r < 2; r++) {
            int v = tid + r*256;
            int row = v >> 2;
            int kq  = (v & 3) * 4;
            int gn = bn + row;
            float4 f = (gn < NO) ? *(const float4*)(W + (size_t)gn*128 + k0 + kq)
                                 : make_float4(0.f,0.f,0.f,0.f);
            Bs[kq+0][row] = f.x; Bs[kq+1][row] = f.y;
            Bs[kq+2][row] = f.z; Bs[kq+3][row] = f.w;
        }
        __syncthreads();
        #pragma unroll
        for (int k = 0; k < BK; k++) {
            float a[8], b[8];
            #pragma unroll
            for (int i = 0; i < 4; i++) { a[i] = As[k][rm0+i]; a[i+4] = As[k][rm1+i]; }
            #pragma unroll
            for (int j = 0; j < 4; j++) { b[j] = Bs[k][cn0+j]; b[j+4] = Bs[k][cn1+j]; }
            #pragma unroll
            for (int i = 0; i < 8; i++)
                #pragma unroll
                for (int j = 0; j < 8; j++) acc[i][j] = fmaf(a[i], b[j], acc[i][j]);
        }
        __syncthreads();
    }
    #pragma unroll
    for (int i = 0; i < 8; i++) {
        int gm = bm + ((i < 4) ? rm0 + i : rm1 + i - 4);
        if (gm >= M) continue;
        #pragma unroll
        for (int j = 0; j < 8; j++) {
            int gn = bn + ((j < 4) ? cn0 + j : cn1 + j - 4);
            if (gn < NO) C[(size_t)gm*NO + gn] = acc[i][j];
        }
    }
}

// ---------------- 128-dim mean-agg + bias + self + relu ----------------
// one warp per (branch, node): out = relu(mean_nbr(t) + bias + r)
__global__ void k_agg128(const float* __restrict__ t, const float* __restrict__ r,
                         const float* __restrict__ bias,
                         float* __restrict__ hout, float* __restrict__ dout)
{
    int w = (blockIdx.x*blockDim.x + threadIdx.x) >> 5;
    int lane = threadIdx.x & 31;
    if (w >= 2*NN) return;
    int b = (w >= NN);
    int i = w - b*NN;
    int base = b*NN;
    int e0 = g_off[i], e1 = g_off[i+1];
    float4 acc = make_float4(0.f,0.f,0.f,0.f);
    for (int e = e0; e < e1; e++) {
        int j = g_csr[e];
        float4 v = *(const float4*)(t + ((size_t)(base + j) << 7) + (lane << 2));
        acc.x += v.x; acc.y += v.y; acc.z += v.z; acc.w += v.w;
    }
    float inv = (e1 > e0) ? 1.f/(float)(e1 - e0) : 0.f;
    float4 bb = *(const float4*)(bias + (lane << 2));
    float4 rr = *(const float4*)(r + ((size_t)w << 7) + (lane << 2));
    float4 o;
    o.x = fmaxf(fmaf(acc.x, inv, bb.x + rr.x), 0.f);
    o.y = fmaxf(fmaf(acc.y, inv, bb.y + rr.y), 0.f);
    o.z = fmaxf(fmaf(acc.z, inv, bb.z + rr.z), 0.f);
    o.w = fmaxf(fmaf(acc.w, inv, bb.w + rr.w), 0.f);
    *(float4*)(hout + ((size_t)w << 7) + (lane << 2)) = o;
    if (dout) {
        *(float4*)(dout + (size_t)b*OPB + (size_t)i*DH + (lane << 2)) = o;
    }
}

// ---------------- 47-dim agg + bias + self, z and log_softmax(y) ----------------
// one warp per (branch, node); lane covers features 2*lane, 2*lane+1
__global__ void k_agg47(const float* __restrict__ t2, const float* __restrict__ r2,
                        const float* __restrict__ bias, float* __restrict__ dout)
{
    int w = (blockIdx.x*blockDim.x + threadIdx.x) >> 5;
    int lane = threadIdx.x & 31;
    if (w >= 2*NN) return;
    int b = (w >= NN);
    int i = w - b*NN;
    int base = b*NN;
    int f0 = lane*2, f1 = lane*2 + 1;
    bool v0 = (f0 < DO), v1 = (f1 < DO);
    int e0 = g_off[i], e1 = g_off[i+1];
    float a0 = 0.f, a1 = 0.f;
    for (int e = e0; e < e1; e++) {
        const float* row = t2 + (size_t)(base + g_csr[e]) * DO;
        if (v0) a0 += row[f0];
        if (v1) a1 += row[f1];
    }
    float inv = (e1 > e0) ? 1.f/(float)(e1 - e0) : 0.f;
    float z0 = v0 ? fmaf(a0, inv, bias[f0] + r2[(size_t)w*DO + f0]) : -INFINITY;
    float z1 = v1 ? fmaf(a1, inv, bias[f1] + r2[(size_t)w*DO + f1]) : -INFINITY;
    float m = fmaxf(z0, z1);
    #pragma unroll
    for (int o = 16; o; o >>= 1) m = fmaxf(m, __shfl_xor_sync(0xffffffffu, m, o));
    float s = (v0 ? expf(z0 - m) : 0.f) + (v1 ? expf(z1 - m) : 0.f);
    #pragma unroll
    for (int o = 16; o; o >>= 1) s += __shfl_xor_sync(0xffffffffu, s, o);
    float lse = m + logf(s);
    float* ybase = dout + (size_t)b*OPB + (size_t)NN*DH          + (size_t)i*DO;
    float* zbase = dout + (size_t)b*OPB + (size_t)NN*(DH + DO)   + (size_t)i*DO;
    if (v0) { zbase[f0] = z0; ybase[f0] = z0 - lse; }
    if (v1) { zbase[f1] = z1; ybase[f1] = z1 - lse; }
}

// ---------------- orchestration ----------------
extern "C" void kernel_launch(void* const* d_in, const int* in_sizes, int n_in,
                              void* d_out, int out_size)
{
    const float* x     = (const float*)d_in[0];
    const int*   ei    = (const int*)  d_in[1];
    const float* noise = (const float*)d_in[2];
    const float* Wl0   = (const float*)d_in[3];
    const float* bl0   = (const float*)d_in[4];
    const float* Wr0   = (const float*)d_in[5];
    const float* Wl1   = (const float*)d_in[6];
    const float* bl1   = (const float*)d_in[7];
    const float* Wr1   = (const float*)d_in[8];
    const float* Wl2   = (const float*)d_in[9];
    const float* bl2   = (const float*)d_in[10];
    const float* Wr2   = (const float*)d_in[11];
    float* out = (float*)d_out;

    float *px2, *pt, *pr, *ph, *pt2, *pr2;
    cudaGetSymbolAddress((void**)&px2, g_x2);
    cudaGetSymbolAddress((void**)&pt,  g_t);
    cudaGetSymbolAddress((void**)&pr,  g_r);
    cudaGetSymbolAddress((void**)&ph,  g_h);
    cudaGetSymbolAddress((void**)&pt2, g_t2);
    cudaGetSymbolAddress((void**)&pr2, g_r2);

    const int M = 2*NN;

    // noise branch input + copy of clean input
    k_noise<<<(NN*32 + 255)/256, 256>>>(x, noise);

    // CSR build (degree histogram, exclusive scan, atomic fill)
    k_zero <<<(NN + 255)/256, 256>>>();
    k_hist <<<(NE + 255)/256, 256>>>(ei);
    k_scan1<<<NB_SCAN, 1024>>>();
    k_scan2<<<1, 64>>>();
    k_scan3<<<NB_SCAN, 1024>>>();
    k_fill <<<(NE + 255)/256, 256>>>(ei);

    dim3 gg((M + BM - 1)/BM, 1);
    int aggBlocks = (2*NN*32 + 255)/256;

    // layer 0: t = x2@Wl0^T, r = x2@Wr0^T, h1 = relu(agg(t) + b + r)
    k_gemm<<<gg, 256>>>(px2, Wl0, pt, M, DH);
    k_gemm<<<gg, 256>>>(px2, Wr0, pr, M, DH);
    k_agg128<<<aggBlocks, 256>>>(pt, pr, bl0, ph, nullptr);

    // layer 1: h2 = relu(agg(h1@Wl1^T) + b + h1@Wr1^T)  -> scratch + d_out h slots
    k_gemm<<<gg, 256>>>(ph, Wl1, pt, M, DH);
    k_gemm<<<gg, 256>>>(ph, Wr1, pr, M, DH);
    k_agg128<<<aggBlocks, 256>>>(pt, pr, bl1, px2, out);

    // layer 2: z = agg(h2@Wl2^T) + b + h2@Wr2^T ; y = log_softmax(z)
    k_gemm<<<gg, 256>>>(px2, Wl2, pt2, M, DO);
    k_gemm<<<gg, 256>>>(px2, Wr2, pr2, M, DO);
    k_agg47<<<aggBlocks, 256>>>(pt2, pr2, bl2, out);
}

// round 4
// speedup vs baseline: 1.5884x; 1.5884x over previous
#include <cuda_runtime.h>
#include <cuda_bf16.h>
#include <math.h>
#include <stdint.h>

#define NN 50000
#define NE 800000
#define DH 128
#define DO 47
#define MM (2*NN)
#define OPB (NN*(DH+DO+DO))
#define NB_SCAN ((NN + 1023)/1024)

// ---------------- scratch ----------------
__device__ float g_x2[MM*DH];
__device__ float g_t [MM*DH];
__device__ float g_r [MM*DH];
__device__ float g_h [MM*DH];
__device__ float g_t2[MM*DO];
__device__ float g_r2[MM*DO];
__device__ int   g_deg[NN];
__device__ int   g_off[NN+1];
__device__ int   g_pos[NN];
__device__ int   g_csr[NE];
__device__ int   g_bsum[64];
// swizzled bf16 weight images: L0 hi/lo 64KB each, L1 hi/lo, L2 hi/lo 32KB each
__device__ __align__(16) uint8_t g_wimg[2*65536 + 2*65536 + 2*32768];

// ---------------- helpers ----------------
__device__ __forceinline__ uint32_t smem_u32(const void* p) {
    uint32_t a;
    asm("{ .reg .u64 t; cvta.to.shared.u64 t, %1; cvt.u32.u64 %0, t; }" : "=r"(a) : "l"(p));
    return a;
}
__device__ __forceinline__ void ldsm4(uint32_t* r, uint32_t addr) {
    asm volatile("ldmatrix.sync.aligned.m8n8.x4.shared.b16 {%0,%1,%2,%3}, [%4];"
        : "=r"(r[0]), "=r"(r[1]), "=r"(r[2]), "=r"(r[3]) : "r"(addr));
}
__device__ __forceinline__ void mma16816(float* c, const uint32_t* a, uint32_t b0, uint32_t b1) {
    asm volatile("mma.sync.aligned.m16n8k16.row.col.f32.bf16.bf16.f32 "
        "{%0,%1,%2,%3}, {%4,%5,%6,%7}, {%8,%9}, {%0,%1,%2,%3};"
        : "+f"(c[0]), "+f"(c[1]), "+f"(c[2]), "+f"(c[3])
        : "r"(a[0]), "r"(a[1]), "r"(a[2]), "r"(a[3]), "r"(b0), "r"(b1));
}
__device__ __forceinline__ void cvt_hilo(const float* v, uint32_t* hp, uint32_t* lp) {
    #pragma unroll
    for (int p = 0; p < 4; p++) {
        __nv_bfloat162 h2 = __floats2bfloat162_rn(v[2*p], v[2*p+1]);
        float l0 = v[2*p]   - __low2float(h2);
        float l1 = v[2*p+1] - __high2float(h2);
        __nv_bfloat162 l2 = __floats2bfloat162_rn(l0, l1);
        hp[p] = *(uint32_t*)&h2;
        lp[p] = *(uint32_t*)&l2;
    }
}

// ---------------- noise ----------------
__global__ void k_noise(const float* __restrict__ x, const float* __restrict__ noise) {
    int w = (blockIdx.x*blockDim.x + threadIdx.x) >> 5;
    int lane = threadIdx.x & 31;
    if (w >= NN) return;
    const float4 nv = *(const float4*)(noise + (size_t)w*DH + lane*4);
    float ss = nv.x*nv.x + nv.y*nv.y + nv.z*nv.z + nv.w*nv.w;
    #pragma unroll
    for (int o = 16; o; o >>= 1) ss += __shfl_xor_sync(0xffffffffu, ss, o);
    float sc = 0.1f / fmaxf(sqrtf(ss), 1e-12f);
    float4 xv = *(const float4*)(x + (size_t)w*DH + lane*4);
    float4 xn;
    xn.x = xv.x + ((xv.x>0.f)?1.f:((xv.x<0.f)?-1.f:0.f)) * nv.x * sc;
    xn.y = xv.y + ((xv.y>0.f)?1.f:((xv.y<0.f)?-1.f:0.f)) * nv.y * sc;
    xn.z = xv.z + ((xv.z>0.f)?1.f:((xv.z<0.f)?-1.f:0.f)) * nv.z * sc;
    xn.w = xv.w + ((xv.w>0.f)?1.f:((xv.w<0.f)?-1.f:0.f)) * nv.w * sc;
    *(float4*)(g_x2 + (size_t)w*DH      + lane*4) = xv;
    *(float4*)(g_x2 + (size_t)(NN+w)*DH + lane*4) = xn;
}

// ---------------- CSR build ----------------
__global__ void k_zero() {
    int i = blockIdx.x*blockDim.x + threadIdx.x;
    if (i < NN) g_deg[i] = 0;
    if (i < 64) g_bsum[i] = 0;
}
__global__ void k_hist(const int* __restrict__ ei) {
    int e = blockIdx.x*blockDim.x + threadIdx.x;
    if (e < NE) atomicAdd(&g_deg[ei[NE + e]], 1);
}
__global__ void k_scan1() {
    __shared__ int s[1024];
    int tid = threadIdx.x;
    int gid = blockIdx.x*1024 + tid;
    int v = (gid < NN) ? g_deg[gid] : 0;
    s[tid] = v; __syncthreads();
    for (int o = 1; o < 1024; o <<= 1) {
        int t = (tid >= o) ? s[tid-o] : 0;
        __syncthreads(); s[tid] += t; __syncthreads();
    }
    if (gid < NN) g_off[gid+1] = s[tid];
    if (tid == 1023) g_bsum[blockIdx.x] = s[1023];
}
__global__ void k_scan2() {
    __shared__ int s[64];
    int tid = threadIdx.x;
    int v = g_bsum[tid];
    s[tid] = v; __syncthreads();
    for (int o = 1; o < 64; o <<= 1) {
        int t = (tid >= o) ? s[tid-o] : 0;
        __syncthreads(); s[tid] += t; __syncthreads();
    }
    g_bsum[tid] = s[tid] - v;
}
__global__ void k_scan3() {
    int gid = blockIdx.x*1024 + threadIdx.x;
    if (gid >= NN) return;
    int incl = g_off[gid+1] + g_bsum[blockIdx.x];
    g_off[gid+1] = incl;
    g_pos[gid]   = incl - g_deg[gid];
    if (gid == 0) g_off[0] = 0;
}
__global__ void k_fill(const int* __restrict__ ei) {
    int e = blockIdx.x*blockDim.x + threadIdx.x;
    if (e < NE) {
        int dst = ei[NE + e];
        int p = atomicAdd(&g_pos[dst], 1);
        g_csr[p] = ei[e];
    }
}

// ---------------- weight -> swizzled bf16 hi/lo images ----------------
// image layout: [NB rows][256 B]; 16B chunk c8 stored at ((c8 ^ (row&7))<<4)
__global__ void k_wconv(const float* Wl0, const float* Wr0,
                        const float* Wl1, const float* Wr1,
                        const float* Wl2, const float* Wr2) {
    int id = blockIdx.x*blockDim.x + threadIdx.x;
    const float* src = nullptr;
    uint8_t *imgHi, *imgLo;
    int row, c8;
    if (id < 4096) {                       // L0: 256 rows
        row = id >> 4; c8 = id & 15;
        imgHi = g_wimg;          imgLo = g_wimg + 65536;
        src = (row < 128) ? (Wl0 + (size_t)row*128) : (Wr0 + (size_t)(row-128)*128);
    } else if (id < 8192) {                // L1: 256 rows
        id -= 4096; row = id >> 4; c8 = id & 15;
        imgHi = g_wimg + 131072; imgLo = g_wimg + 196608;
        src = (row < 128) ? (Wl1 + (size_t)row*128) : (Wr1 + (size_t)(row-128)*128);
    } else if (id < 10240) {               // L2: 128 rows ([Wl2|0|Wr2|0])
        id -= 8192; row = id >> 4; c8 = id & 15;
        imgHi = g_wimg + 262144; imgLo = g_wimg + 294912;
        if (row < 47)                     src = Wl2 + (size_t)row*128;
        else if (row >= 64 && row < 111)  src = Wr2 + (size_t)(row-64)*128;
        else                              src = nullptr;
    } else return;
    float v[8];
    #pragma unroll
    for (int j = 0; j < 8; j++) v[j] = src ? src[c8*8 + j] : 0.f;
    uint32_t hp[4], lp[4];
    cvt_hilo(v, hp, lp);
    uint32_t off = (uint32_t)row*256u + (uint32_t)((c8 ^ (row & 7)) << 4);
    *(uint4*)(imgHi + off) = make_uint4(hp[0], hp[1], hp[2], hp[3]);
    *(uint4*)(imgLo + off) = make_uint4(lp[0], lp[1], lp[2], lp[3]);
}

// ---------------- mma.sync bf16-split GEMM ----------------
// CTA tile 128x128. smem: Ah[0,32K) Al[32K,64K) Bh[64K,96K) Bl[96K,128K)
// 3 terms: Ah*Bh + Ah*Bl + Al*Bh. grid.y selects 128-col weight slice.
template<bool SPLIT47>
__global__ void __launch_bounds__(256) k_gemm_mma(
    const float* __restrict__ X, const uint8_t* __restrict__ imgHi,
    const uint8_t* __restrict__ imgLo,
    float* __restrict__ out0, float* __restrict__ out1, int M)
{
    extern __shared__ char smem[];
    const int tid = threadIdx.x;
    const int bm = blockIdx.x * 128;
    const int g  = blockIdx.y;
    uint32_t sb = smem_u32(smem);

    // A fill: fp32 -> bf16 hi/lo, chunk-swizzled
    #pragma unroll
    for (int i = 0; i < 8; i++) {
        int id = tid + i*256;
        int row = id >> 4, c8 = id & 15;
        int gm = bm + row;
        float v[8];
        if (gm < M) {
            float4 f0 = *(const float4*)(X + (size_t)gm*128 + c8*8);
            float4 f1 = *(const float4*)(X + (size_t)gm*128 + c8*8 + 4);
            v[0]=f0.x; v[1]=f0.y; v[2]=f0.z; v[3]=f0.w;
            v[4]=f1.x; v[5]=f1.y; v[6]=f1.z; v[7]=f1.w;
        } else {
            #pragma unroll
            for (int j = 0; j < 8; j++) v[j] = 0.f;
        }
        uint32_t hp[4], lp[4];
        cvt_hilo(v, hp, lp);
        uint32_t off = (uint32_t)row*256u + (uint32_t)((c8 ^ (row & 7)) << 4);
        *(uint4*)(smem + off)         = make_uint4(hp[0], hp[1], hp[2], hp[3]);
        *(uint4*)(smem + 32768 + off) = make_uint4(lp[0], lp[1], lp[2], lp[3]);
    }
    // B copy: pre-swizzled 32KB hi + 32KB lo slice
    {
        const uint4* bh = (const uint4*)(imgHi + (size_t)g*32768);
        const uint4* bl = (const uint4*)(imgLo + (size_t)g*32768);
        #pragma unroll
        for (int i = 0; i < 8; i++) {
            int id = tid + i*256;
            ((uint4*)(smem + 65536))[id] = bh[id];
            ((uint4*)(smem + 98304))[id] = bl[id];
        }
    }
    __syncthreads();

    const int lane = tid & 31, w = tid >> 5;
    const int tm = (w >> 1) * 32, tn = (w & 1) * 64;
    const int lrow = lane & 15, lsel = lane >> 4;

    float acc[2][8][4];
    #pragma unroll
    for (int a = 0; a < 2; a++)
        #pragma unroll
        for (int b = 0; b < 8; b++)
            #pragma unroll
            for (int c = 0; c < 4; c++) acc[a][b][c] = 0.f;

    #pragma unroll
    for (int term = 0; term < 3; term++) {
        uint32_t abase = sb + (term == 2 ? 32768u : 0u);
        uint32_t bbase = sb + (term == 1 ? 98304u : 65536u);
        #pragma unroll
        for (int k16 = 0; k16 < 8; k16++) {
            const int c8 = k16*2 + lsel;
            uint32_t a[2][4];
            #pragma unroll
            for (int mt = 0; mt < 2; mt++) {
                int row = tm + mt*16 + lrow;
                ldsm4(a[mt], abase + (uint32_t)row*256u + (uint32_t)((c8 ^ (row & 7)) << 4));
            }
            uint32_t b[4][4];
            #pragma unroll
            for (int bt = 0; bt < 4; bt++) {
                int n = tn + bt*16 + lrow;
                ldsm4(b[bt], bbase + (uint32_t)n*256u + (uint32_t)((c8 ^ (n & 7)) << 4));
            }
            #pragma unroll
            for (int mt = 0; mt < 2; mt++)
                #pragma unroll
                for (int bt = 0; bt < 4; bt++) {
                    mma16816(acc[mt][bt*2+0], a[mt], b[bt][0], b[bt][2]);
                    mma16816(acc[mt][bt*2+1], a[mt], b[bt][1], b[bt][3]);
                }
        }
    }

    // epilogue
    if constexpr (!SPLIT47) {
        float* dst = g ? out1 : out0;
        #pragma unroll
        for (int mt = 0; mt < 2; mt++) {
            int r0 = bm + tm + mt*16 + (lane >> 2);
            int r1 = r0 + 8;
            #pragma unroll
            for (int nt = 0; nt < 8; nt++) {
                int col = tn + nt*8 + (lane & 3)*2;
                if (r0 < M) *(float2*)(dst + (size_t)r0*128 + col)
                    = make_float2(acc[mt][nt][0], acc[mt][nt][1]);
                if (r1 < M) *(float2*)(dst + (size_t)r1*128 + col)
                    = make_float2(acc[mt][nt][2], acc[mt][nt][3]);
            }
        }
    } else {
        float* dst = (w & 1) ? out1 : out0;   // cols 0-63 -> t2, 64-127 -> r2
        #pragma unroll
        for (int mt = 0; mt < 2; mt++) {
            int r0 = bm + tm + mt*16 + (lane >> 2);
            int r1 = r0 + 8;
            #pragma unroll
            for (int nt = 0; nt < 8; nt++) {
                int cl = nt*8 + (lane & 3)*2;
                if (cl < DO) {
                    if (r0 < M) dst[(size_t)r0*DO + cl] = acc[mt][nt][0];
                    if (r1 < M) dst[(size_t)r1*DO + cl] = acc[mt][nt][2];
                }
                if (cl + 1 < DO) {
                    if (r0 < M) dst[(size_t)r0*DO + cl + 1] = acc[mt][nt][1];
                    if (r1 < M) dst[(size_t)r1*DO + cl + 1] = acc[mt][nt][3];
                }
            }
        }
    }
}

// ---------------- 128-dim mean-agg + bias + self + relu ----------------
__global__ void k_agg128(const float* __restrict__ t, const float* __restrict__ r,
                         const float* __restrict__ bias,
                         float* __restrict__ hout, float* __restrict__ dout)
{
    int w = (blockIdx.x*blockDim.x + threadIdx.x) >> 5;
    int lane = threadIdx.x & 31;
    if (w >= MM) return;
    int b = (w >= NN);
    int i = w - b*NN;
    int base = b*NN;
    int e0 = g_off[i], e1 = g_off[i+1];
    float4 acc = make_float4(0.f,0.f,0.f,0.f);
    for (int e = e0; e < e1; e++) {
        int j = g_csr[e];
        float4 v = *(const float4*)(t + ((size_t)(base + j) << 7) + (lane << 2));
        acc.x += v.x; acc.y += v.y; acc.z += v.z; acc.w += v.w;
    }
    float inv = (e1 > e0) ? 1.f/(float)(e1 - e0) : 0.f;
    float4 bb = *(const float4*)(bias + (lane << 2));
    float4 rr = *(const float4*)(r + ((size_t)w << 7) + (lane << 2));
    float4 o;
    o.x = fmaxf(fmaf(acc.x, inv, bb.x + rr.x), 0.f);
    o.y = fmaxf(fmaf(acc.y, inv, bb.y + rr.y), 0.f);
    o.z = fmaxf(fmaf(acc.z, inv, bb.z + rr.z), 0.f);
    o.w = fmaxf(fmaf(acc.w, inv, bb.w + rr.w), 0.f);
    *(float4*)(hout + ((size_t)w << 7) + (lane << 2)) = o;
    if (dout) {
        *(float4*)(dout + (size_t)b*OPB + (size_t)i*DH + (lane << 2)) = o;
    }
}

// ---------------- 47-dim agg + bias + self, z and log_softmax(y) ----------------
__global__ void k_agg47(const float* __restrict__ t2, const float* __restrict__ r2,
                        const float* __restrict__ bias, float* __restrict__ dout)
{
    int w = (blockIdx.x*blockDim.x + threadIdx.x) >> 5;
    int lane = threadIdx.x & 31;
    if (w >= MM) return;
    int b = (w >= NN);
    int i = w - b*NN;
    int base = b*NN;
    int f0 = lane*2, f1 = lane*2 + 1;
    bool v0 = (f0 < DO), v1 = (f1 < DO);
    int e0 = g_off[i], e1 = g_off[i+1];
    float a0 = 0.f, a1 = 0.f;
    for (int e = e0; e < e1; e++) {
        const float* row = t2 + (size_t)(base + g_csr[e]) * DO;
        if (v0) a0 += row[f0];
        if (v1) a1 += row[f1];
    }
    float inv = (e1 > e0) ? 1.f/(float)(e1 - e0) : 0.f;
    float z0 = v0 ? fmaf(a0, inv, bias[f0] + r2[(size_t)w*DO + f0]) : -INFINITY;
    float z1 = v1 ? fmaf(a1, inv, bias[f1] + r2[(size_t)w*DO + f1]) : -INFINITY;
    float m = fmaxf(z0, z1);
    #pragma unroll
    for (int o = 16; o; o >>= 1) m = fmaxf(m, __shfl_xor_sync(0xffffffffu, m, o));
    float s = (v0 ? expf(z0 - m) : 0.f) + (v1 ? expf(z1 - m) : 0.f);
    #pragma unroll
    for (int o = 16; o; o >>= 1) s += __shfl_xor_sync(0xffffffffu, s, o);
    float lse = m + logf(s);
    float* ybase = dout + (size_t)b*OPB + (size_t)NN*DH        + (size_t)i*DO;
    float* zbase = dout + (size_t)b*OPB + (size_t)NN*(DH + DO) + (size_t)i*DO;
    if (v0) { zbase[f0] = z0; ybase[f0] = z0 - lse; }
    if (v1) { zbase[f1] = z1; ybase[f1] = z1 - lse; }
}

// ---------------- orchestration ----------------
extern "C" void kernel_launch(void* const* d_in, const int* in_sizes, int n_in,
                              void* d_out, int out_size)
{
    const float* x     = (const float*)d_in[0];
    const int*   ei    = (const int*)  d_in[1];
    const float* noise = (const float*)d_in[2];
    const float* Wl0   = (const float*)d_in[3];
    const float* bl0   = (const float*)d_in[4];
    const float* Wr0   = (const float*)d_in[5];
    const float* Wl1   = (const float*)d_in[6];
    const float* bl1   = (const float*)d_in[7];
    const float* Wr1   = (const float*)d_in[8];
    const float* Wl2   = (const float*)d_in[9];
    const float* bl2   = (const float*)d_in[10];
    const float* Wr2   = (const float*)d_in[11];
    float* out = (float*)d_out;

    float *px2, *pt, *pr, *ph, *pt2, *pr2;
    uint8_t* pw;
    cudaGetSymbolAddress((void**)&px2, g_x2);
    cudaGetSymbolAddress((void**)&pt,  g_t);
    cudaGetSymbolAddress((void**)&pr,  g_r);
    cudaGetSymbolAddress((void**)&ph,  g_h);
    cudaGetSymbolAddress((void**)&pt2, g_t2);
    cudaGetSymbolAddress((void**)&pr2, g_r2);
    cudaGetSymbolAddress((void**)&pw,  g_wimg);

    const int SM = 131072;
    cudaFuncSetAttribute(k_gemm_mma<false>, cudaFuncAttributeMaxDynamicSharedMemorySize, SM);
    cudaFuncSetAttribute(k_gemm_mma<true>,  cudaFuncAttributeMaxDynamicSharedMemorySize, SM);

    // noise branch + clean copy
    k_noise<<<(NN*32 + 255)/256, 256>>>(x, noise);

    // CSR build
    k_zero <<<(NN + 255)/256, 256>>>();
    k_hist <<<(NE + 255)/256, 256>>>(ei);
    k_scan1<<<NB_SCAN, 1024>>>();
    k_scan2<<<1, 64>>>();
    k_scan3<<<NB_SCAN, 1024>>>();
    k_fill <<<(NE + 255)/256, 256>>>(ei);

    // weight images
    k_wconv<<<40, 256>>>(Wl0, Wr0, Wl1, Wr1, Wl2, Wr2);

    dim3 gBig((MM + 127)/128, 2);
    dim3 gSml((MM + 127)/128, 1);
    int aggBlocks = (MM*32 + 255)/256;

    // layer 0
    k_gemm_mma<false><<<gBig, 256, SM>>>(px2, pw, pw + 65536, pt, pr, MM);
    k_agg128<<<aggBlocks, 256>>>(pt, pr, bl0, ph, nullptr);

    // layer 1
    k_gemm_mma<false><<<gBig, 256, SM>>>(ph, pw + 131072, pw + 196608, pt, pr, MM);
    k_agg128<<<aggBlocks, 256>>>(pt, pr, bl1, px2, out);

    // layer 2
    k_gemm_mma<true><<<gSml, 256, SM>>>(px2, pw + 262144, pw + 294912, pt2, pr2, MM);
    k_agg47<<<aggBlocks, 256>>>(pt2, pr2, bl2, out);
}